// round 10
// baseline (speedup 1.0000x reference)
#include <cuda_runtime.h>
#include <cstdint>

static constexpr int N    = 1024;
static constexpr int EMAX = 524288;
static constexpr int HB   = 256;   // histogram blocks

// ---------------- device scratch ----------------
__device__ int   g_bh[HB * N];
__device__ int   g_tot[N];
__device__ int   g_base[N];
__device__ int   g_off[N + 1];
__device__ int   g_src[EMAX];
__device__ float g_A1[N * 64];
__device__ float g_B1[N * 64];
__device__ float g_A2[N * 64];
__device__ float g_B2[N * 64];
__device__ float g_h2[N * 512];

__device__ __forceinline__ float neg_inf() { return __int_as_float(0xff800000); }

// pack two fp32 into fp16x2: lo -> low half, hi -> high half
__device__ __forceinline__ uint32_t pack_h2(float lo, float hi) {
    uint32_t r;
    asm("cvt.rn.f16x2.f32 %0, %1, %2;" : "=r"(r) : "f"(hi), "f"(lo));
    return r;
}

__device__ __forceinline__ uint32_t f2tf(float f) {
    uint32_t u;
    asm("cvt.rna.tf32.f32 %0, %1;" : "=r"(u) : "f"(f));
    return u;
}

__device__ __forceinline__ void mma_f16(float d[4], const uint4& a,
                                        const uint32_t b[2]) {
    asm volatile(
        "mma.sync.aligned.m16n8k16.row.col.f32.f16.f16.f32 "
        "{%0,%1,%2,%3}, {%4,%5,%6,%7}, {%8,%9}, {%0,%1,%2,%3};"
        : "+f"(d[0]), "+f"(d[1]), "+f"(d[2]), "+f"(d[3])
        : "r"(a.x), "r"(a.y), "r"(a.z), "r"(a.w), "r"(b[0]), "r"(b[1]));
}

__device__ __forceinline__ void mma_tf32(float d[4], const uint32_t a[4],
                                         const uint32_t b[2]) {
    asm volatile(
        "mma.sync.aligned.m16n8k8.row.col.f32.tf32.tf32.f32 "
        "{%0,%1,%2,%3}, {%4,%5,%6,%7}, {%8,%9}, {%0,%1,%2,%3};"
        : "+f"(d[0]), "+f"(d[1]), "+f"(d[2]), "+f"(d[3])
        : "r"(a[0]), "r"(a[1]), "r"(a[2]), "r"(a[3]), "r"(b[0]), "r"(b[1]));
}

// ---------------- sort pipeline ----------------
// In-CTA dtype detection: if edges are int32 but read as int64, a value in
// [0,N) requires the high word to be 0 — probability ~N^-16 over 16 samples.
__device__ __forceinline__ int detect_is64(const void* edges) {
    const long long* q = (const long long*)edges;
    int ok = 1;
#pragma unroll
    for (int i = 0; i < 16; i++) {
        long long v = q[i];
        if (v < 0 || v >= N) ok = 0;
    }
    return ok;
}

// load 4 consecutive edge indices starting at e0 (e0 % 4 == 0) via 16B loads
__device__ __forceinline__ void load4(const void* edges, long long off, int e0,
                                      int is64, int out[4]) {
    if (is64) {
        const long long* p = (const long long*)edges + off + e0;
        longlong2 v0 = *(const longlong2*)p;
        longlong2 v1 = *(const longlong2*)(p + 2);
        out[0] = (int)v0.x; out[1] = (int)v0.y;
        out[2] = (int)v1.x; out[3] = (int)v1.y;
    } else {
        int4 v = *(const int4*)((const int*)edges + off + e0);
        out[0] = v.x; out[1] = v.y; out[2] = v.z; out[3] = v.w;
    }
}

__global__ void k_hist2(const void* edges, int E) {
    __shared__ int h[N];
    __shared__ int sis64;
    int b = blockIdx.x, tid = threadIdx.x;
    for (int i = tid; i < N; i += 512) h[i] = 0;
    if (tid == 0) sis64 = detect_is64(edges);
    __syncthreads();
    int is64 = sis64;
    int per = (E + HB - 1) / HB;
    int s0 = b * per, s1 = min(E, s0 + per);
    for (int e0 = s0 + tid * 4; e0 < s1; e0 += 2048) {
        if (e0 + 4 <= s1) {
            int d[4];
            load4(edges, E, e0, is64, d);
#pragma unroll
            for (int j = 0; j < 4; j++) atomicAdd(&h[d[j]], 1);
        } else {
            for (int e = e0; e < s1; e++) {
                int d = is64 ? (int)((const long long*)edges)[(long long)E + e]
                             : ((const int*)edges)[E + e];
                atomicAdd(&h[d], 1);
            }
        }
    }
    __syncthreads();
    for (int i = tid; i < N; i += 512) g_bh[b * N + i] = h[i];
}

// per-dst exclusive scan over the HB block-histograms.
__global__ void k_scanA() {
    __shared__ int s[16][32];
    int tid = threadIdx.x;
    int dlane = tid & 31, bg = tid >> 5;
    int d = blockIdx.x * 32 + dlane;
    int v[16], sum = 0;
#pragma unroll
    for (int j = 0; j < 16; j++) v[j] = g_bh[(bg * 16 + j) * N + d];
#pragma unroll
    for (int j = 0; j < 16; j++) { int t = v[j]; v[j] = sum; sum += t; }
    s[bg][dlane] = sum;
    __syncthreads();
    int base = 0;
#pragma unroll
    for (int k = 0; k < 16; k++) {
        int val = s[k][dlane];
        if (k < bg) base += val;
    }
    if (bg == 15) g_tot[d] = base + sum;
#pragma unroll
    for (int j = 0; j < 16; j++) g_bh[(bg * 16 + j) * N + d] = base + v[j];
}

__global__ void k_scanB() {
    __shared__ int s[N];
    int d = threadIdx.x;
    int tot = g_tot[d];
    s[d] = tot;
    __syncthreads();
    for (int off = 1; off < N; off <<= 1) {
        int v = (d >= off) ? s[d - off] : 0;
        __syncthreads();
        s[d] += v;
        __syncthreads();
    }
    g_off[d + 1] = s[d];
    if (d == 0) g_off[0] = 0;
    g_base[d] = s[d] - tot;
}

__global__ void k_scatter2(const void* edges, int E) {
    __shared__ int h[N];
    __shared__ int bhs[N];
    __shared__ int sis64;
    int b = blockIdx.x, tid = threadIdx.x;
    for (int i = tid; i < N; i += 512) {
        h[i] = 0;
        bhs[i] = g_base[i] + g_bh[b * N + i];
    }
    if (tid == 0) sis64 = detect_is64(edges);
    __syncthreads();
    int is64 = sis64;
    int per = (E + HB - 1) / HB;
    int s0 = b * per, s1 = min(E, s0 + per);
    for (int e0 = s0 + tid * 4; e0 < s1; e0 += 2048) {
        if (e0 + 4 <= s1) {
            int d[4], sv[4];
            load4(edges, E, e0, is64, d);
            load4(edges, 0, e0, is64, sv);
#pragma unroll
            for (int j = 0; j < 4; j++) {
                int pos = bhs[d[j]] + atomicAdd(&h[d[j]], 1);
                g_src[pos] = sv[j];
            }
        } else {
            for (int e = e0; e < s1; e++) {
                int d, sv;
                if (is64) {
                    sv = (int)((const long long*)edges)[e];
                    d  = (int)((const long long*)edges)[(long long)E + e];
                } else {
                    sv = ((const int*)edges)[e];
                    d  = ((const int*)edges)[E + e];
                }
                int pos = bhs[d] + atomicAdd(&h[d], 1);
                g_src[pos] = sv;
            }
        }
    }
}

// ---------------- per-node A/B precompute (layer 1) ----------------
__global__ void k_pre1(const float* __restrict__ x, const float* __restrict__ W1,
                       const float* __restrict__ b1) {
    __shared__ float xr[64];
    int n = blockIdx.x, j = threadIdx.x;
    xr[j] = x[n * 64 + j];
    __syncthreads();
    float a = b1[j], b = 0.f;
#pragma unroll 8
    for (int k = 0; k < 64; k++) {
        float xv = xr[k];
        a = fmaf(xv, W1[k * 64 + j], a);
        b = fmaf(xv, W1[(64 + k) * 64 + j], b);
    }
    g_A1[n * 64 + j] = a;
    g_B1[n * 64 + j] = b;
}

// ---------------- tensor-core (mma.sync fp16 m16n8k16) EdgeConv ----------------
// (unchanged from R9 — 256 threads, 2 CTAs/SM co-residency)
template <int C_OUT, int EG, int SPLIT, bool FUSE>
__global__ void __launch_bounds__(256, 2)
k_conv_mma(const float* __restrict__ Avec, const float* __restrict__ Bvec,
           const float* __restrict__ W, const float* __restrict__ bias,
           float* __restrict__ out, float* __restrict__ outB,
           const float* __restrict__ W3, const float* __restrict__ b3) {
    constexpr int THREADS = 256;
    constexpr int CPC = C_OUT / SPLIT;
    constexpr int CG  = 8 / EG;
    constexpr int NT  = (CPC / CG) / 8;
    __shared__ __align__(16) uint4 Ps4[2048];
    __shared__ __align__(16) float avs[64];
    __shared__ float red[(EG > 1 ? EG : 1) * CPC];
    __shared__ float hs[FUSE ? 128 : 1];

    int tid = threadIdx.x, lane = tid & 31;
    int wid = tid >> 5;
    int g = lane >> 2, tig = lane & 3;
    int cgrp = wid / EG, egrp = wid % EG;
    int n = blockIdx.x / SPLIT;
    int csplit = blockIdx.x % SPLIT;
    int cbase = csplit * CPC + cgrp * (NT * 8);

    if (tid < 64) avs[tid] = Avec[n * 64 + tid];

    uint32_t wf[4][NT][2];
#pragma unroll
    for (int s = 0; s < 4; s++)
#pragma unroll
        for (int t = 0; t < NT; t++) {
            int c = cbase + t * 8 + g;
            int k0 = s * 16 + 2 * tig;
            wf[s][t][0] = pack_h2(W[k0 * C_OUT + c], W[(k0 + 1) * C_OUT + c]);
            wf[s][t][1] = pack_h2(W[(k0 + 8) * C_OUT + c], W[(k0 + 9) * C_OUT + c]);
        }

    float mx[NT][2];
#pragma unroll
    for (int t = 0; t < NT; t++) { mx[t][0] = neg_inf(); mx[t][1] = neg_inf(); }

    int beg = g_off[n], end = g_off[n + 1];

    auto build = [&](int bufi, int t0, int cnt) {
#pragma unroll
        for (int it = 0; it < 4; it++) {
            int idx = tid + it * THREADS;
            int m = idx >> 7, s = (idx >> 5) & 3, L = idx & 31;
            if (m * 16 < cnt) {
                int gg = L >> 2, tt = L & 3;
                int e0 = m * 16 + gg;
                int i0 = min(t0 + e0, end - 1);
                int i1 = min(t0 + e0 + 8, end - 1);
                const float* B0 = Bvec + g_src[i0] * 64;
                const float* B1 = Bvec + g_src[i1] * 64;
                int k0 = s * 16 + 2 * tt;
                float2 a0 = *(const float2*)(avs + k0);
                float2 a1 = *(const float2*)(avs + k0 + 8);
                float2 p0 = *(const float2*)(B0 + k0);
                float2 p1 = *(const float2*)(B1 + k0);
                float2 q0 = *(const float2*)(B0 + k0 + 8);
                float2 q1 = *(const float2*)(B1 + k0 + 8);
                uint4 v;
                v.x = pack_h2(fmaxf(a0.x + p0.x, 0.f), fmaxf(a0.y + p0.y, 0.f));
                v.y = pack_h2(fmaxf(a0.x + p1.x, 0.f), fmaxf(a0.y + p1.y, 0.f));
                v.z = pack_h2(fmaxf(a1.x + q0.x, 0.f), fmaxf(a1.y + q0.y, 0.f));
                v.w = pack_h2(fmaxf(a1.x + q1.x, 0.f), fmaxf(a1.y + q1.y, 0.f));
                Ps4[bufi * 1024 + (m * 32 + L) * 4 + ((s + (L >> 1)) & 3)] = v;
            }
        }
    };

    __syncthreads();
    if (beg < end) build(0, beg, min(128, end - beg));
    __syncthreads();

    int buf = 0;
    for (int t0 = beg; t0 < end; t0 += 128, buf ^= 1) {
        int cnt = min(128, end - t0);
        for (int m = egrp; m < 8; m += EG) {
            if (m * 16 >= cnt) break;
            float acc4[NT][4];
#pragma unroll
            for (int t = 0; t < NT; t++) {
                acc4[t][0] = 0.f; acc4[t][1] = 0.f;
                acc4[t][2] = 0.f; acc4[t][3] = 0.f;
            }
#pragma unroll
            for (int s = 0; s < 4; s++) {
                uint4 q = Ps4[buf * 1024 + (m * 32 + lane) * 4 + ((s + (lane >> 1)) & 3)];
#pragma unroll
                for (int t = 0; t < NT; t++) mma_f16(acc4[t], q, wf[s][t]);
            }
            int r0 = m * 16 + g;
            bool v0 = r0 < cnt, v1 = (r0 + 8) < cnt;
#pragma unroll
            for (int t = 0; t < NT; t++) {
                if (v0) { mx[t][0] = fmaxf(mx[t][0], acc4[t][0]);
                          mx[t][1] = fmaxf(mx[t][1], acc4[t][1]); }
                if (v1) { mx[t][0] = fmaxf(mx[t][0], acc4[t][2]);
                          mx[t][1] = fmaxf(mx[t][1], acc4[t][3]); }
            }
        }
        int nt0 = t0 + 128;
        if (nt0 < end) build(buf ^ 1, nt0, min(128, end - nt0));
        __syncthreads();
    }

#pragma unroll
    for (int t = 0; t < NT; t++)
#pragma unroll
        for (int off = 4; off < 32; off <<= 1) {
            mx[t][0] = fmaxf(mx[t][0], __shfl_xor_sync(0xffffffffu, mx[t][0], off));
            mx[t][1] = fmaxf(mx[t][1], __shfl_xor_sync(0xffffffffu, mx[t][1], off));
        }

    if (EG == 1) {
        if (lane < 4) {
#pragma unroll
            for (int t = 0; t < NT; t++) {
                int c = cbase + t * 8 + 2 * tig;
                float v0 = mx[t][0], v1 = mx[t][1];
                out[n * C_OUT + c]     = (v0 == neg_inf()) ? 0.f : v0 + bias[c];
                out[n * C_OUT + c + 1] = (v1 == neg_inf()) ? 0.f : v1 + bias[c + 1];
            }
        }
    } else {
        if (lane < 4) {
#pragma unroll
            for (int t = 0; t < NT; t++) {
                int c = cbase + t * 8 + 2 * tig;
                red[egrp * C_OUT + c]     = mx[t][0];
                red[egrp * C_OUT + c + 1] = mx[t][1];
            }
        }
        __syncthreads();
        for (int c = tid; c < C_OUT; c += THREADS) {
            float m = red[c];
#pragma unroll
            for (int e = 1; e < EG; e++) m = fmaxf(m, red[e * C_OUT + c]);
            float hv = (m == neg_inf()) ? 0.f : m + bias[c];
            if (FUSE) hs[c] = hv;
            else out[n * C_OUT + c] = hv;
        }
    }

    if (FUSE) {
        __syncthreads();
        if (tid < 128) {
            int half = tid >> 6;
            int j = tid & 63;
            const float* Wc = W3 + half * 128 * 64;
            float a0 = half ? 0.f : b3[j];
            float a1 = 0.f;
#pragma unroll 8
            for (int k = 0; k < 128; k += 2) {
                a0 = fmaf(hs[k],     Wc[k * 64 + j],       a0);
                a1 = fmaf(hs[k + 1], Wc[(k + 1) * 64 + j], a1);
            }
            (half ? outB : out)[n * 64 + j] = a0 + a1;
        }
    }
}

// ---------------- readout (tf32 tensor): out[i][j] = sum_n h2[n][i]*Wr[n][j] + br[j]
// CTA = 128 threads (4 warps), 64x64 output tile, K=1024 in chunks of 32.
// A[m=i][k=n] = h2[n][i] (staged k-major), B[k=n][j] = Wr[n][j].
// m16n8k8.tf32 frags: A a0=[g,tig] a1=[g+8,tig] a2=[g,tig+4] a3=[g+8,tig+4];
// B b0=[tig,col g] b1=[tig+4,col g]; D d0=[g,2tig] d1=[g,2tig+1] d2/d3 rows+8.
__global__ void __launch_bounds__(128)
k_readout_tc(const float* __restrict__ Wr, const float* __restrict__ br,
             float* __restrict__ out) {
    __shared__ uint32_t As[32][68];
    __shared__ uint32_t Bs[32][68];
    int i0 = blockIdx.y * 64, j0 = blockIdx.x * 64;
    int tid = threadIdx.x, lane = tid & 31, w = tid >> 5;
    int g = lane >> 2, tig = lane & 3;
    int wi = w * 16;

    float acc[8][4];
#pragma unroll
    for (int t = 0; t < 8; t++) {
        acc[t][0] = 0.f; acc[t][1] = 0.f; acc[t][2] = 0.f; acc[t][3] = 0.f;
    }

    for (int n0 = 0; n0 < N; n0 += 32) {
        for (int idx = tid; idx < 32 * 64; idx += 128) {
            int kk = idx >> 6, col = idx & 63;
            As[kk][col] = f2tf(g_h2[(n0 + kk) * 512 + i0 + col]);
            Bs[kk][col] = f2tf(Wr[(n0 + kk) * 512 + j0 + col]);
        }
        __syncthreads();
#pragma unroll
        for (int k8 = 0; k8 < 32; k8 += 8) {
            uint32_t a[4];
            a[0] = As[k8 + tig][wi + g];
            a[1] = As[k8 + tig][wi + g + 8];
            a[2] = As[k8 + tig + 4][wi + g];
            a[3] = As[k8 + tig + 4][wi + g + 8];
#pragma unroll
            for (int t = 0; t < 8; t++) {
                uint32_t b[2];
                b[0] = Bs[k8 + tig][t * 8 + g];
                b[1] = Bs[k8 + tig + 4][t * 8 + g];
                mma_tf32(acc[t], a, b);
            }
        }
        __syncthreads();
    }

    int row0 = i0 + wi + g, row1 = row0 + 8;
#pragma unroll
    for (int t = 0; t < 8; t++) {
        int col = j0 + t * 8 + 2 * tig;
        float bc0 = br[col], bc1 = br[col + 1];
        out[row0 * 512 + col]     = acc[t][0] + bc0;
        out[row0 * 512 + col + 1] = acc[t][1] + bc1;
        out[row1 * 512 + col]     = acc[t][2] + bc0;
        out[row1 * 512 + col + 1] = acc[t][3] + bc1;
    }
}

extern "C" void kernel_launch(void* const* d_in, const int* in_sizes, int n_in,
                              void* d_out, int out_size) {
    const float* x  = (const float*)d_in[0];
    const void*  ei = d_in[1];
    const float* W1 = (const float*)d_in[2];
    const float* b1 = (const float*)d_in[3];
    const float* W2 = (const float*)d_in[4];
    const float* b2 = (const float*)d_in[5];
    const float* W3 = (const float*)d_in[6];
    const float* b3 = (const float*)d_in[7];
    const float* W4 = (const float*)d_in[8];
    const float* b4 = (const float*)d_in[9];
    const float* Wr = (const float*)d_in[10];
    const float* br = (const float*)d_in[11];

    int E = in_sizes[1] / 2;
    if (E > EMAX) E = EMAX;

    float *pA1, *pB1, *pA2, *pB2, *ph2;
    cudaGetSymbolAddress((void**)&pA1, g_A1);
    cudaGetSymbolAddress((void**)&pB1, g_B1);
    cudaGetSymbolAddress((void**)&pA2, g_A2);
    cudaGetSymbolAddress((void**)&pB2, g_B2);
    cudaGetSymbolAddress((void**)&ph2, g_h2);

    k_hist2<<<HB, 512>>>(ei, E);
    k_pre1<<<N, 64>>>(x, W1, b1);
    k_scanA<<<32, 512>>>();
    k_scanB<<<1, 1024>>>();
    k_scatter2<<<HB, 512>>>(ei, E);
    // conv1 (fused pre2): 1 CTA/node, 256 threads, EG=2
    k_conv_mma<128, 2, 1, true><<<N, 256>>>(pA1, pB1, W2, b2, pA2, pB2, W3, b3);
    // conv2: 2 CTAs/node (channel halves), 256 threads, EG=1
    k_conv_mma<512, 1, 2, false><<<2 * N, 256>>>(pA2, pB2, W4, b4, ph2, nullptr, nullptr, nullptr);
    k_readout_tc<<<dim3(8, 8), 128>>>(Wr, br, (float*)d_out);
}

// round 11
// speedup vs baseline: 1.1808x; 1.1808x over previous
#include <cuda_runtime.h>
#include <cstdint>

static constexpr int N    = 1024;
static constexpr int EMAX = 524288;
static constexpr int HB   = 256;   // histogram blocks

// ---------------- device scratch ----------------
__device__ int   g_is64;
__device__ int   g_bh[HB * N];
__device__ int   g_tot[N];
__device__ int   g_base[N];
__device__ int   g_off[N + 1];
__device__ int   g_src[EMAX];
__device__ float g_A1[N * 64];
__device__ float g_B1[N * 64];
__device__ float g_A2[N * 64];
__device__ float g_B2[N * 64];
__device__ float g_h2[N * 512];

__device__ __forceinline__ float neg_inf() { return __int_as_float(0xff800000); }

// pack two fp32 into fp16x2: lo -> low half, hi -> high half
__device__ __forceinline__ uint32_t pack_h2(float lo, float hi) {
    uint32_t r;
    asm("cvt.rn.f16x2.f32 %0, %1, %2;" : "=r"(r) : "f"(hi), "f"(lo));
    return r;
}

__device__ __forceinline__ void mma_f16(float d[4], const uint4& a,
                                        const uint32_t b[2]) {
    asm volatile(
        "mma.sync.aligned.m16n8k16.row.col.f32.f16.f16.f32 "
        "{%0,%1,%2,%3}, {%4,%5,%6,%7}, {%8,%9}, {%0,%1,%2,%3};"
        : "+f"(d[0]), "+f"(d[1]), "+f"(d[2]), "+f"(d[3])
        : "r"(a.x), "r"(a.y), "r"(a.z), "r"(a.w), "r"(b[0]), "r"(b[1]));
}

// ---------------- sort pipeline (R7/R9, known-good) ----------------
__device__ __forceinline__ int edge_val(const void* p, long long i, int is64) {
    if (is64) return (int)((const long long*)p)[i];
    return ((const int*)p)[i];
}

__global__ void k_detect(const void* edges) {
    if (threadIdx.x == 0) {
        const long long* q = (const long long*)edges;
        int ok = 1;
        for (int i = 0; i < 64; i++) {
            long long v = q[i];
            if (v < 0 || v >= N) { ok = 0; break; }
        }
        g_is64 = ok;
    }
}

__global__ void k_hist2(const void* edges, int E) {
    __shared__ int h[N];
    int b = blockIdx.x, tid = threadIdx.x;
    for (int i = tid; i < N; i += 512) h[i] = 0;
    __syncthreads();
    int is64 = g_is64;
    int per = (E + HB - 1) / HB;
    int s0 = b * per, s1 = min(E, s0 + per);
    for (int base = s0; base < s1; base += 2048) {
        int d[4];
#pragma unroll
        for (int j = 0; j < 4; j++) {
            int e = base + tid + j * 512;
            d[j] = (e < s1) ? edge_val(edges, (long long)E + e, is64) : -1;
        }
#pragma unroll
        for (int j = 0; j < 4; j++)
            if (d[j] >= 0) atomicAdd(&h[d[j]], 1);
    }
    __syncthreads();
    for (int i = tid; i < N; i += 512) g_bh[b * N + i] = h[i];
}

// per-dst exclusive scan over the HB block-histograms.
__global__ void k_scanA() {
    __shared__ int s[16][32];
    int tid = threadIdx.x;
    int dlane = tid & 31, bg = tid >> 5;
    int d = blockIdx.x * 32 + dlane;
    int v[16], sum = 0;
#pragma unroll
    for (int j = 0; j < 16; j++) v[j] = g_bh[(bg * 16 + j) * N + d];
#pragma unroll
    for (int j = 0; j < 16; j++) { int t = v[j]; v[j] = sum; sum += t; }
    s[bg][dlane] = sum;
    __syncthreads();
    int base = 0;
#pragma unroll
    for (int k = 0; k < 16; k++) {
        int val = s[k][dlane];
        if (k < bg) base += val;
    }
    if (bg == 15) g_tot[d] = base + sum;
#pragma unroll
    for (int j = 0; j < 16; j++) g_bh[(bg * 16 + j) * N + d] = base + v[j];
}

__global__ void k_scanB() {
    __shared__ int s[N];
    int d = threadIdx.x;
    int tot = g_tot[d];
    s[d] = tot;
    __syncthreads();
    for (int off = 1; off < N; off <<= 1) {
        int v = (d >= off) ? s[d - off] : 0;
        __syncthreads();
        s[d] += v;
        __syncthreads();
    }
    g_off[d + 1] = s[d];
    if (d == 0) g_off[0] = 0;
    g_base[d] = s[d] - tot;
}

__global__ void k_scatter2(const void* edges, int E) {
    __shared__ int h[N];
    __shared__ int bhs[N];
    int b = blockIdx.x, tid = threadIdx.x;
    for (int i = tid; i < N; i += 512) {
        h[i] = 0;
        bhs[i] = g_base[i] + g_bh[b * N + i];
    }
    __syncthreads();
    int is64 = g_is64;
    int per = (E + HB - 1) / HB;
    int s0 = b * per, s1 = min(E, s0 + per);
    for (int base = s0; base < s1; base += 2048) {
        int d[4], sv[4];
#pragma unroll
        for (int j = 0; j < 4; j++) {
            int e = base + tid + j * 512;
            if (e < s1) {
                sv[j] = edge_val(edges, e, is64);
                d[j]  = edge_val(edges, (long long)E + e, is64);
            } else d[j] = -1;
        }
#pragma unroll
        for (int j = 0; j < 4; j++)
            if (d[j] >= 0) {
                int pos = bhs[d[j]] + atomicAdd(&h[d[j]], 1);
                g_src[pos] = sv[j];
            }
    }
}

// ---------------- per-node A/B precompute (layer 1) ----------------
__global__ void k_pre1(const float* __restrict__ x, const float* __restrict__ W1,
                       const float* __restrict__ b1) {
    __shared__ float xr[64];
    int n = blockIdx.x, j = threadIdx.x;
    xr[j] = x[n * 64 + j];
    __syncthreads();
    float a = b1[j], b = 0.f;
#pragma unroll 8
    for (int k = 0; k < 64; k++) {
        float xv = xr[k];
        a = fmaf(xv, W1[k * 64 + j], a);
        b = fmaf(xv, W1[(64 + k) * 64 + j], b);
    }
    g_A1[n * 64 + j] = a;
    g_B1[n * 64 + j] = b;
}

// ---------------- tensor-core (mma.sync fp16 m16n8k16) EdgeConv ----------------
// 256 threads = 8 warps per CTA; MAXCTA CTAs co-resident per SM so one CTA's
// MMAs cover another CTA's gather/build stalls.
// SPLIT = channel-split CTAs per node (conv2: 2, each owning C_OUT/SPLIT chans).
// P tile (128 edges x 64 k, fp16) fragment-major, double-buffered:
//   uint4 slot [buf*1024 + (m*32+L)*4 + ((s+(L>>1))&3)]; rotation =>
//   conflict-free STS.128 / LDS.128.
// FUSE: epilogue computes A2/B2 = f(h1[n]) in-place (fused pre2).
template <int C_OUT, int EG, int SPLIT, bool FUSE, int MAXCTA>
__global__ void __launch_bounds__(256, MAXCTA)
k_conv_mma(const float* __restrict__ Avec, const float* __restrict__ Bvec,
           const float* __restrict__ W, const float* __restrict__ bias,
           float* __restrict__ out, float* __restrict__ outB,
           const float* __restrict__ W3, const float* __restrict__ b3) {
    constexpr int THREADS = 256;
    constexpr int CPC = C_OUT / SPLIT;
    constexpr int CG  = 8 / EG;
    constexpr int NT  = (CPC / CG) / 8;
    __shared__ __align__(16) uint4 Ps4[2048];
    __shared__ __align__(16) float avs[64];
    __shared__ float red[(EG > 1 ? EG : 1) * CPC];
    __shared__ float hs[FUSE ? 128 : 1];

    int tid = threadIdx.x, lane = tid & 31;
    int wid = tid >> 5;
    int g = lane >> 2, tig = lane & 3;
    int cgrp = wid / EG, egrp = wid % EG;
    int n = blockIdx.x / SPLIT;
    int csplit = blockIdx.x % SPLIT;
    int cbase = csplit * CPC + cgrp * (NT * 8);

    if (tid < 64) avs[tid] = Avec[n * 64 + tid];

    uint32_t wf[4][NT][2];
#pragma unroll
    for (int s = 0; s < 4; s++)
#pragma unroll
        for (int t = 0; t < NT; t++) {
            int c = cbase + t * 8 + g;
            int k0 = s * 16 + 2 * tig;
            wf[s][t][0] = pack_h2(W[k0 * C_OUT + c], W[(k0 + 1) * C_OUT + c]);
            wf[s][t][1] = pack_h2(W[(k0 + 8) * C_OUT + c], W[(k0 + 9) * C_OUT + c]);
        }

    float mx[NT][2];
#pragma unroll
    for (int t = 0; t < NT; t++) { mx[t][0] = neg_inf(); mx[t][1] = neg_inf(); }

    int beg = g_off[n], end = g_off[n + 1];

    auto build = [&](int bufi, int t0, int cnt) {
#pragma unroll
        for (int it = 0; it < 4; it++) {
            int idx = tid + it * THREADS;
            int m = idx >> 7, s = (idx >> 5) & 3, L = idx & 31;
            if (m * 16 < cnt) {
                int gg = L >> 2, tt = L & 3;
                int e0 = m * 16 + gg;
                int i0 = min(t0 + e0, end - 1);
                int i1 = min(t0 + e0 + 8, end - 1);
                const float* B0 = Bvec + g_src[i0] * 64;
                const float* B1 = Bvec + g_src[i1] * 64;
                int k0 = s * 16 + 2 * tt;
                float2 a0 = *(const float2*)(avs + k0);
                float2 a1 = *(const float2*)(avs + k0 + 8);
                float2 p0 = *(const float2*)(B0 + k0);
                float2 p1 = *(const float2*)(B1 + k0);
                float2 q0 = *(const float2*)(B0 + k0 + 8);
                float2 q1 = *(const float2*)(B1 + k0 + 8);
                uint4 v;
                v.x = pack_h2(fmaxf(a0.x + p0.x, 0.f), fmaxf(a0.y + p0.y, 0.f));
                v.y = pack_h2(fmaxf(a0.x + p1.x, 0.f), fmaxf(a0.y + p1.y, 0.f));
                v.z = pack_h2(fmaxf(a1.x + q0.x, 0.f), fmaxf(a1.y + q0.y, 0.f));
                v.w = pack_h2(fmaxf(a1.x + q1.x, 0.f), fmaxf(a1.y + q1.y, 0.f));
                Ps4[bufi * 1024 + (m * 32 + L) * 4 + ((s + (L >> 1)) & 3)] = v;
            }
        }
    };

    __syncthreads();
    if (beg < end) build(0, beg, min(128, end - beg));
    __syncthreads();

    int buf = 0;
    for (int t0 = beg; t0 < end; t0 += 128, buf ^= 1) {
        int cnt = min(128, end - t0);
        for (int m = egrp; m < 8; m += EG) {
            if (m * 16 >= cnt) break;
            float acc4[NT][4];
#pragma unroll
            for (int t = 0; t < NT; t++) {
                acc4[t][0] = 0.f; acc4[t][1] = 0.f;
                acc4[t][2] = 0.f; acc4[t][3] = 0.f;
            }
#pragma unroll
            for (int s = 0; s < 4; s++) {
                uint4 q = Ps4[buf * 1024 + (m * 32 + lane) * 4 + ((s + (lane >> 1)) & 3)];
#pragma unroll
                for (int t = 0; t < NT; t++) mma_f16(acc4[t], q, wf[s][t]);
            }
            int r0 = m * 16 + g;
            bool v0 = r0 < cnt, v1 = (r0 + 8) < cnt;
#pragma unroll
            for (int t = 0; t < NT; t++) {
                if (v0) { mx[t][0] = fmaxf(mx[t][0], acc4[t][0]);
                          mx[t][1] = fmaxf(mx[t][1], acc4[t][1]); }
                if (v1) { mx[t][0] = fmaxf(mx[t][0], acc4[t][2]);
                          mx[t][1] = fmaxf(mx[t][1], acc4[t][3]); }
            }
        }
        int nt0 = t0 + 128;
        if (nt0 < end) build(buf ^ 1, nt0, min(128, end - nt0));
        __syncthreads();
    }

#pragma unroll
    for (int t = 0; t < NT; t++)
#pragma unroll
        for (int off = 4; off < 32; off <<= 1) {
            mx[t][0] = fmaxf(mx[t][0], __shfl_xor_sync(0xffffffffu, mx[t][0], off));
            mx[t][1] = fmaxf(mx[t][1], __shfl_xor_sync(0xffffffffu, mx[t][1], off));
        }

    if (EG == 1) {
        if (lane < 4) {
#pragma unroll
            for (int t = 0; t < NT; t++) {
                int c = cbase + t * 8 + 2 * tig;
                float v0 = mx[t][0], v1 = mx[t][1];
                out[n * C_OUT + c]     = (v0 == neg_inf()) ? 0.f : v0 + bias[c];
                out[n * C_OUT + c + 1] = (v1 == neg_inf()) ? 0.f : v1 + bias[c + 1];
            }
        }
    } else {
        if (lane < 4) {
#pragma unroll
            for (int t = 0; t < NT; t++) {
                int c = cbase + t * 8 + 2 * tig;
                red[egrp * C_OUT + c]     = mx[t][0];
                red[egrp * C_OUT + c + 1] = mx[t][1];
            }
        }
        __syncthreads();
        for (int c = tid; c < C_OUT; c += THREADS) {
            float m = red[c];
#pragma unroll
            for (int e = 1; e < EG; e++) m = fmaxf(m, red[e * C_OUT + c]);
            float hv = (m == neg_inf()) ? 0.f : m + bias[c];
            if (FUSE) hs[c] = hv;
            else out[n * C_OUT + c] = hv;
        }
    }

    if (FUSE) {
        __syncthreads();
        if (tid < 128) {
            int half = tid >> 6;
            int j = tid & 63;
            const float* Wc = W3 + half * 128 * 64;
            float a0 = half ? 0.f : b3[j];
            float a1 = 0.f;
#pragma unroll 8
            for (int k = 0; k < 128; k += 2) {
                a0 = fmaf(hs[k],     Wc[k * 64 + j],       a0);
                a1 = fmaf(hs[k + 1], Wc[(k + 1) * 64 + j], a1);
            }
            (half ? outB : out)[n * 64 + j] = a0 + a1;
        }
    }
}

// ---------------- readout (R9 fp32 version): out[i][j] = sum_n h2[n][i]*Wr[n][j] + br[j]
__global__ void k_readout(const float* __restrict__ Wr, const float* __restrict__ br,
                          float* __restrict__ out) {
    __shared__ float As[16][64];
    __shared__ float Bs[16][64];
    int i0 = blockIdx.y * 64, j0 = blockIdx.x * 64;
    int tid = threadIdx.x;
    int jt = tid & 15, it = tid >> 4;
    float c[4][4];
#pragma unroll
    for (int r = 0; r < 4; r++)
#pragma unroll
        for (int s = 0; s < 4; s++) c[r][s] = 0.f;

    for (int n0 = 0; n0 < N; n0 += 16) {
        for (int idx = tid; idx < 16 * 64; idx += 256) {
            int kk = idx >> 6, col = idx & 63;
            As[kk][col] = g_h2[(n0 + kk) * 512 + i0 + col];
            Bs[kk][col] = Wr[(n0 + kk) * 512 + j0 + col];
        }
        __syncthreads();
#pragma unroll
        for (int kk = 0; kk < 16; kk++) {
            float a[4], b[4];
#pragma unroll
            for (int r = 0; r < 4; r++) a[r] = As[kk][it * 4 + r];
#pragma unroll
            for (int s = 0; s < 4; s++) b[s] = Bs[kk][jt * 4 + s];
#pragma unroll
            for (int r = 0; r < 4; r++)
#pragma unroll
                for (int s = 0; s < 4; s++) c[r][s] = fmaf(a[r], b[s], c[r][s]);
        }
        __syncthreads();
    }
#pragma unroll
    for (int r = 0; r < 4; r++)
#pragma unroll
        for (int s = 0; s < 4; s++)
            out[(i0 + it * 4 + r) * 512 + j0 + jt * 4 + s] = c[r][s] + br[j0 + jt * 4 + s];
}

extern "C" void kernel_launch(void* const* d_in, const int* in_sizes, int n_in,
                              void* d_out, int out_size) {
    const float* x  = (const float*)d_in[0];
    const void*  ei = d_in[1];
    const float* W1 = (const float*)d_in[2];
    const float* b1 = (const float*)d_in[3];
    const float* W2 = (const float*)d_in[4];
    const float* b2 = (const float*)d_in[5];
    const float* W3 = (const float*)d_in[6];
    const float* b3 = (const float*)d_in[7];
    const float* W4 = (const float*)d_in[8];
    const float* b4 = (const float*)d_in[9];
    const float* Wr = (const float*)d_in[10];
    const float* br = (const float*)d_in[11];

    int E = in_sizes[1] / 2;
    if (E > EMAX) E = EMAX;

    float *pA1, *pB1, *pA2, *pB2, *ph2;
    cudaGetSymbolAddress((void**)&pA1, g_A1);
    cudaGetSymbolAddress((void**)&pB1, g_B1);
    cudaGetSymbolAddress((void**)&pA2, g_A2);
    cudaGetSymbolAddress((void**)&pB2, g_B2);
    cudaGetSymbolAddress((void**)&ph2, g_h2);

    k_detect<<<1, 32>>>(ei);
    k_hist2<<<HB, 512>>>(ei, E);
    k_pre1<<<N, 64>>>(x, W1, b1);
    k_scanA<<<32, 512>>>();
    k_scanB<<<1, 1024>>>();
    k_scatter2<<<HB, 512>>>(ei, E);
    // conv1 (fused pre2): 1 CTA/node, 256 threads, EG=2, 2 CTAs/SM
    k_conv_mma<128, 2, 1, true, 2><<<N, 256>>>(pA1, pB1, W2, b2, pA2, pB2, W3, b3);
    // conv2: 2 CTAs/node (channel halves), 256 threads, EG=1, 3 CTAs/SM
    k_conv_mma<512, 1, 2, false, 3><<<2 * N, 256>>>(pA2, pB2, W4, b4, ph2, nullptr, nullptr, nullptr);
    k_readout<<<dim3(8, 8), 256>>>(Wr, br, (float*)d_out);
}

// round 12
// speedup vs baseline: 1.2136x; 1.0277x over previous
#include <cuda_runtime.h>
#include <cstdint>

static constexpr int N    = 1024;
static constexpr int EMAX = 524288;
static constexpr int HB   = 256;   // histogram blocks

// ---------------- device scratch ----------------
__device__ int   g_is64;
__device__ int   g_bh[HB * N];
__device__ int   g_tot[N];
__device__ int   g_base[N];
__device__ int   g_off[N + 1];
__device__ int   g_src[EMAX];
__device__ float g_A1[N * 64];
__device__ float g_B1[N * 64];
__device__ float g_A2[N * 64];
__device__ float g_B2[N * 64];
__device__ float g_h2[N * 512];

__device__ __forceinline__ float neg_inf() { return __int_as_float(0xff800000); }

// pack two fp32 into fp16x2: lo -> low half, hi -> high half
__device__ __forceinline__ uint32_t pack_h2(float lo, float hi) {
    uint32_t r;
    asm("cvt.rn.f16x2.f32 %0, %1, %2;" : "=r"(r) : "f"(hi), "f"(lo));
    return r;
}

__device__ __forceinline__ void mma_f16(float d[4], const uint4& a,
                                        const uint32_t b[2]) {
    asm volatile(
        "mma.sync.aligned.m16n8k16.row.col.f32.f16.f16.f32 "
        "{%0,%1,%2,%3}, {%4,%5,%6,%7}, {%8,%9}, {%0,%1,%2,%3};"
        : "+f"(d[0]), "+f"(d[1]), "+f"(d[2]), "+f"(d[3])
        : "r"(a.x), "r"(a.y), "r"(a.z), "r"(a.w), "r"(b[0]), "r"(b[1]));
}

// ---------------- sort pipeline (R7/R9, known-good) ----------------
__device__ __forceinline__ int edge_val(const void* p, long long i, int is64) {
    if (is64) return (int)((const long long*)p)[i];
    return ((const int*)p)[i];
}

__global__ void k_detect(const void* edges) {
    if (threadIdx.x == 0) {
        const long long* q = (const long long*)edges;
        int ok = 1;
        for (int i = 0; i < 64; i++) {
            long long v = q[i];
            if (v < 0 || v >= N) { ok = 0; break; }
        }
        g_is64 = ok;
    }
}

__global__ void k_hist2(const void* edges, int E) {
    __shared__ int h[N];
    int b = blockIdx.x, tid = threadIdx.x;
    for (int i = tid; i < N; i += 512) h[i] = 0;
    __syncthreads();
    int is64 = g_is64;
    int per = (E + HB - 1) / HB;
    int s0 = b * per, s1 = min(E, s0 + per);
    for (int base = s0; base < s1; base += 2048) {
        int d[4];
#pragma unroll
        for (int j = 0; j < 4; j++) {
            int e = base + tid + j * 512;
            d[j] = (e < s1) ? edge_val(edges, (long long)E + e, is64) : -1;
        }
#pragma unroll
        for (int j = 0; j < 4; j++)
            if (d[j] >= 0) atomicAdd(&h[d[j]], 1);
    }
    __syncthreads();
    for (int i = tid; i < N; i += 512) g_bh[b * N + i] = h[i];
}

// per-dst exclusive scan over the HB block-histograms.
__global__ void k_scanA() {
    __shared__ int s[16][32];
    int tid = threadIdx.x;
    int dlane = tid & 31, bg = tid >> 5;
    int d = blockIdx.x * 32 + dlane;
    int v[16], sum = 0;
#pragma unroll
    for (int j = 0; j < 16; j++) v[j] = g_bh[(bg * 16 + j) * N + d];
#pragma unroll
    for (int j = 0; j < 16; j++) { int t = v[j]; v[j] = sum; sum += t; }
    s[bg][dlane] = sum;
    __syncthreads();
    int base = 0;
#pragma unroll
    for (int k = 0; k < 16; k++) {
        int val = s[k][dlane];
        if (k < bg) base += val;
    }
    if (bg == 15) g_tot[d] = base + sum;
#pragma unroll
    for (int j = 0; j < 16; j++) g_bh[(bg * 16 + j) * N + d] = base + v[j];
}

__global__ void k_scanB() {
    __shared__ int s[N];
    int d = threadIdx.x;
    int tot = g_tot[d];
    s[d] = tot;
    __syncthreads();
    for (int off = 1; off < N; off <<= 1) {
        int v = (d >= off) ? s[d - off] : 0;
        __syncthreads();
        s[d] += v;
        __syncthreads();
    }
    g_off[d + 1] = s[d];
    if (d == 0) g_off[0] = 0;
    g_base[d] = s[d] - tot;
}

__global__ void k_scatter2(const void* edges, int E) {
    __shared__ int h[N];
    __shared__ int bhs[N];
    int b = blockIdx.x, tid = threadIdx.x;
    for (int i = tid; i < N; i += 512) {
        h[i] = 0;
        bhs[i] = g_base[i] + g_bh[b * N + i];
    }
    __syncthreads();
    int is64 = g_is64;
    int per = (E + HB - 1) / HB;
    int s0 = b * per, s1 = min(E, s0 + per);
    for (int base = s0; base < s1; base += 2048) {
        int d[4], sv[4];
#pragma unroll
        for (int j = 0; j < 4; j++) {
            int e = base + tid + j * 512;
            if (e < s1) {
                sv[j] = edge_val(edges, e, is64);
                d[j]  = edge_val(edges, (long long)E + e, is64);
            } else d[j] = -1;
        }
#pragma unroll
        for (int j = 0; j < 4; j++)
            if (d[j] >= 0) {
                int pos = bhs[d[j]] + atomicAdd(&h[d[j]], 1);
                g_src[pos] = sv[j];
            }
    }
}

// ---------------- per-node A/B precompute (layer 1) ----------------
__global__ void k_pre1(const float* __restrict__ x, const float* __restrict__ W1,
                       const float* __restrict__ b1) {
    __shared__ float xr[64];
    int n = blockIdx.x, j = threadIdx.x;
    xr[j] = x[n * 64 + j];
    __syncthreads();
    float a = b1[j], b = 0.f;
#pragma unroll 8
    for (int k = 0; k < 64; k++) {
        float xv = xr[k];
        a = fmaf(xv, W1[k * 64 + j], a);
        b = fmaf(xv, W1[(64 + k) * 64 + j], b);
    }
    g_A1[n * 64 + j] = a;
    g_B1[n * 64 + j] = b;
}

// ---------------- tensor-core (mma.sync fp16 m16n8k16) EdgeConv ----------------
// 256 threads = 8 warps per CTA; MAXCTA CTAs co-resident per SM so one CTA's
// MMAs cover another CTA's gather/build stalls.
// SPLIT = channel-split CTAs per node (conv2: 2, each owning C_OUT/SPLIT chans).
// P tile (128 edges x 64 k, fp16) fragment-major, double-buffered:
//   uint4 slot [buf*1024 + (m*32+L)*4 + ((s+(L>>1))&3)]; rotation =>
//   conflict-free STS.128 / LDS.128.
// FUSE: epilogue computes A2/B2 = f(h1[n]) in-place (fused pre2).
template <int C_OUT, int EG, int SPLIT, bool FUSE, int MAXCTA>
__global__ void __launch_bounds__(256, MAXCTA)
k_conv_mma(const float* __restrict__ Avec, const float* __restrict__ Bvec,
           const float* __restrict__ W, const float* __restrict__ bias,
           float* __restrict__ out, float* __restrict__ outB,
           const float* __restrict__ W3, const float* __restrict__ b3) {
    constexpr int THREADS = 256;
    constexpr int CPC = C_OUT / SPLIT;
    constexpr int CG  = 8 / EG;
    constexpr int NT  = (CPC / CG) / 8;
    __shared__ __align__(16) uint4 Ps4[2048];
    __shared__ __align__(16) float avs[64];
    __shared__ float red[(EG > 1 ? EG : 1) * CPC];
    __shared__ float hs[FUSE ? 128 : 1];

    int tid = threadIdx.x, lane = tid & 31;
    int wid = tid >> 5;
    int g = lane >> 2, tig = lane & 3;
    int cgrp = wid / EG, egrp = wid % EG;
    int n = blockIdx.x / SPLIT;
    int csplit = blockIdx.x % SPLIT;
    int cbase = csplit * CPC + cgrp * (NT * 8);

    if (tid < 64) avs[tid] = Avec[n * 64 + tid];

    uint32_t wf[4][NT][2];
#pragma unroll
    for (int s = 0; s < 4; s++)
#pragma unroll
        for (int t = 0; t < NT; t++) {
            int c = cbase + t * 8 + g;
            int k0 = s * 16 + 2 * tig;
            wf[s][t][0] = pack_h2(W[k0 * C_OUT + c], W[(k0 + 1) * C_OUT + c]);
            wf[s][t][1] = pack_h2(W[(k0 + 8) * C_OUT + c], W[(k0 + 9) * C_OUT + c]);
        }

    float mx[NT][2];
#pragma unroll
    for (int t = 0; t < NT; t++) { mx[t][0] = neg_inf(); mx[t][1] = neg_inf(); }

    int beg = g_off[n], end = g_off[n + 1];

    auto build = [&](int bufi, int t0, int cnt) {
#pragma unroll
        for (int it = 0; it < 4; it++) {
            int idx = tid + it * THREADS;
            int m = idx >> 7, s = (idx >> 5) & 3, L = idx & 31;
            if (m * 16 < cnt) {
                int gg = L >> 2, tt = L & 3;
                int e0 = m * 16 + gg;
                int i0 = min(t0 + e0, end - 1);
                int i1 = min(t0 + e0 + 8, end - 1);
                const float* B0 = Bvec + g_src[i0] * 64;
                const float* B1 = Bvec + g_src[i1] * 64;
                int k0 = s * 16 + 2 * tt;
                float2 a0 = *(const float2*)(avs + k0);
                float2 a1 = *(const float2*)(avs + k0 + 8);
                float2 p0 = *(const float2*)(B0 + k0);
                float2 p1 = *(const float2*)(B1 + k0);
                float2 q0 = *(const float2*)(B0 + k0 + 8);
                float2 q1 = *(const float2*)(B1 + k0 + 8);
                uint4 v;
                v.x = pack_h2(fmaxf(a0.x + p0.x, 0.f), fmaxf(a0.y + p0.y, 0.f));
                v.y = pack_h2(fmaxf(a0.x + p1.x, 0.f), fmaxf(a0.y + p1.y, 0.f));
                v.z = pack_h2(fmaxf(a1.x + q0.x, 0.f), fmaxf(a1.y + q0.y, 0.f));
                v.w = pack_h2(fmaxf(a1.x + q1.x, 0.f), fmaxf(a1.y + q1.y, 0.f));
                Ps4[bufi * 1024 + (m * 32 + L) * 4 + ((s + (L >> 1)) & 3)] = v;
            }
        }
    };

    __syncthreads();
    if (beg < end) build(0, beg, min(128, end - beg));
    __syncthreads();

    int buf = 0;
    for (int t0 = beg; t0 < end; t0 += 128, buf ^= 1) {
        int cnt = min(128, end - t0);
        for (int m = egrp; m < 8; m += EG) {
            if (m * 16 >= cnt) break;
            float acc4[NT][4];
#pragma unroll
            for (int t = 0; t < NT; t++) {
                acc4[t][0] = 0.f; acc4[t][1] = 0.f;
                acc4[t][2] = 0.f; acc4[t][3] = 0.f;
            }
#pragma unroll
            for (int s = 0; s < 4; s++) {
                uint4 q = Ps4[buf * 1024 + (m * 32 + lane) * 4 + ((s + (lane >> 1)) & 3)];
#pragma unroll
                for (int t = 0; t < NT; t++) mma_f16(acc4[t], q, wf[s][t]);
            }
            int r0 = m * 16 + g;
            bool v0 = r0 < cnt, v1 = (r0 + 8) < cnt;
#pragma unroll
            for (int t = 0; t < NT; t++) {
                if (v0) { mx[t][0] = fmaxf(mx[t][0], acc4[t][0]);
                          mx[t][1] = fmaxf(mx[t][1], acc4[t][1]); }
                if (v1) { mx[t][0] = fmaxf(mx[t][0], acc4[t][2]);
                          mx[t][1] = fmaxf(mx[t][1], acc4[t][3]); }
            }
        }
        int nt0 = t0 + 128;
        if (nt0 < end) build(buf ^ 1, nt0, min(128, end - nt0));
        __syncthreads();
    }

#pragma unroll
    for (int t = 0; t < NT; t++)
#pragma unroll
        for (int off = 4; off < 32; off <<= 1) {
            mx[t][0] = fmaxf(mx[t][0], __shfl_xor_sync(0xffffffffu, mx[t][0], off));
            mx[t][1] = fmaxf(mx[t][1], __shfl_xor_sync(0xffffffffu, mx[t][1], off));
        }

    if (EG == 1) {
        if (lane < 4) {
#pragma unroll
            for (int t = 0; t < NT; t++) {
                int c = cbase + t * 8 + 2 * tig;
                float v0 = mx[t][0], v1 = mx[t][1];
                out[n * C_OUT + c]     = (v0 == neg_inf()) ? 0.f : v0 + bias[c];
                out[n * C_OUT + c + 1] = (v1 == neg_inf()) ? 0.f : v1 + bias[c + 1];
            }
        }
    } else {
        if (lane < 4) {
#pragma unroll
            for (int t = 0; t < NT; t++) {
                int c = cbase + t * 8 + 2 * tig;
                red[egrp * C_OUT + c]     = mx[t][0];
                red[egrp * C_OUT + c + 1] = mx[t][1];
            }
        }
        __syncthreads();
        for (int c = tid; c < C_OUT; c += THREADS) {
            float m = red[c];
#pragma unroll
            for (int e = 1; e < EG; e++) m = fmaxf(m, red[e * C_OUT + c]);
            float hv = (m == neg_inf()) ? 0.f : m + bias[c];
            if (FUSE) hs[c] = hv;
            else out[n * C_OUT + c] = hv;
        }
    }

    if (FUSE) {
        __syncthreads();
        if (tid < 128) {
            int half = tid >> 6;
            int j = tid & 63;
            const float* Wc = W3 + half * 128 * 64;
            float a0 = half ? 0.f : b3[j];
            float a1 = 0.f;
#pragma unroll 8
            for (int k = 0; k < 128; k += 2) {
                a0 = fmaf(hs[k],     Wc[k * 64 + j],       a0);
                a1 = fmaf(hs[k + 1], Wc[(k + 1) * 64 + j], a1);
            }
            (half ? outB : out)[n * 64 + j] = a0 + a1;
        }
    }
}

// ---------------- readout: out[i][j] = sum_n h2[n][i]*Wr[n][j] + br[j] ----------
__global__ void k_readout(const float* __restrict__ Wr, const float* __restrict__ br,
                          float* __restrict__ out) {
    __shared__ float As[16][64];
    __shared__ float Bs[16][64];
    int i0 = blockIdx.y * 64, j0 = blockIdx.x * 64;
    int tid = threadIdx.x;
    int jt = tid & 15, it = tid >> 4;
    float c[4][4];
#pragma unroll
    for (int r = 0; r < 4; r++)
#pragma unroll
        for (int s = 0; s < 4; s++) c[r][s] = 0.f;

    for (int n0 = 0; n0 < N; n0 += 16) {
        for (int idx = tid; idx < 16 * 64; idx += 256) {
            int kk = idx >> 6, col = idx & 63;
            As[kk][col] = g_h2[(n0 + kk) * 512 + i0 + col];
            Bs[kk][col] = Wr[(n0 + kk) * 512 + j0 + col];
        }
        __syncthreads();
#pragma unroll
        for (int kk = 0; kk < 16; kk++) {
            float a[4], b[4];
#pragma unroll
            for (int r = 0; r < 4; r++) a[r] = As[kk][it * 4 + r];
#pragma unroll
            for (int s = 0; s < 4; s++) b[s] = Bs[kk][jt * 4 + s];
#pragma unroll
            for (int r = 0; r < 4; r++)
#pragma unroll
                for (int s = 0; s < 4; s++) c[r][s] = fmaf(a[r], b[s], c[r][s]);
        }
        __syncthreads();
    }
#pragma unroll
    for (int r = 0; r < 4; r++)
#pragma unroll
        for (int s = 0; s < 4; s++)
            out[(i0 + it * 4 + r) * 512 + j0 + jt * 4 + s] = c[r][s] + br[j0 + jt * 4 + s];
}

extern "C" void kernel_launch(void* const* d_in, const int* in_sizes, int n_in,
                              void* d_out, int out_size) {
    const float* x  = (const float*)d_in[0];
    const void*  ei = d_in[1];
    const float* W1 = (const float*)d_in[2];
    const float* b1 = (const float*)d_in[3];
    const float* W2 = (const float*)d_in[4];
    const float* b2 = (const float*)d_in[5];
    const float* W3 = (const float*)d_in[6];
    const float* b3 = (const float*)d_in[7];
    const float* W4 = (const float*)d_in[8];
    const float* b4 = (const float*)d_in[9];
    const float* Wr = (const float*)d_in[10];
    const float* br = (const float*)d_in[11];

    int E = in_sizes[1] / 2;
    if (E > EMAX) E = EMAX;

    float *pA1, *pB1, *pA2, *pB2, *ph2;
    cudaGetSymbolAddress((void**)&pA1, g_A1);
    cudaGetSymbolAddress((void**)&pB1, g_B1);
    cudaGetSymbolAddress((void**)&pA2, g_A2);
    cudaGetSymbolAddress((void**)&pB2, g_B2);
    cudaGetSymbolAddress((void**)&ph2, g_h2);

    k_detect<<<1, 32>>>(ei);
    k_hist2<<<HB, 512>>>(ei, E);
    k_pre1<<<N, 64>>>(x, W1, b1);
    k_scanA<<<32, 512>>>();
    k_scanB<<<1, 1024>>>();
    k_scatter2<<<HB, 512>>>(ei, E);
    // conv1 (fused pre2): 1 CTA/node, 256 threads, EG=2, 3 CTAs/SM
    k_conv_mma<128, 2, 1, true, 3><<<N, 256>>>(pA1, pB1, W2, b2, pA2, pB2, W3, b3);
    // conv2: 2 CTAs/node (channel halves), 256 threads, EG=1, 3 CTAs/SM
    k_conv_mma<512, 1, 2, false, 3><<<2 * N, 256>>>(pA2, pB2, W4, b4, ph2, nullptr, nullptr, nullptr);
    k_readout<<<dim3(8, 8), 256>>>(Wr, br, (float*)d_out);
}